// round 3
// baseline (speedup 1.0000x reference)
#include <cuda_runtime.h>
#include <math.h>

#define L    2048
#define DM   1024
#define NH   16
#define DK   64
#define DFF  4096
#define DI   2048
#define NST  16

// ---------------- scratch (device globals; no allocation allowed) ----------
__device__ float g_h   [L*DM];
__device__ float g_q   [L*DM];
__device__ float g_k   [L*DM];
__device__ float g_v   [L*DM];
__device__ float g_s   [(size_t)NH*L*L];   // 256 MB attention scores
__device__ float g_ao  [L*DM];
__device__ float g_x1  [L*DM];
__device__ float g_mln [L*DM];
__device__ float g_mx  [L*DI];
__device__ float g_cv  [L*DI];
__device__ float g_xdbc[L*96];
__device__ float g_Bm  [L*NST];
__device__ float g_Cm  [L*NST];
__device__ float g_M   [NST*NST];
__device__ float g_Hall[L*NST];
__device__ float g_hd  [L];
__device__ float g_y   [L*DI];
__device__ float g_mo  [L*DM];
__device__ float g_x2  [L*DM];
__device__ float g_h3  [L*DM];
__device__ float g_ff  [(size_t)L*DFF];

// ---------------- LayerNorm (optional affine, optional residual add) -------
__global__ void ln_kernel(const float* __restrict__ in,
                          const float* __restrict__ g,
                          const float* __restrict__ b,
                          const float* __restrict__ res,
                          float* __restrict__ out, int cols)
{
    __shared__ float s1[256], s2[256];
    const float* row = in + (size_t)blockIdx.x * cols;
    float sum = 0.f, sq = 0.f;
    for (int i = threadIdx.x; i < cols; i += 256) {
        float v = row[i]; sum += v; sq += v * v;
    }
    s1[threadIdx.x] = sum; s2[threadIdx.x] = sq;
    __syncthreads();
    for (int s = 128; s > 0; s >>= 1) {
        if (threadIdx.x < s) { s1[threadIdx.x] += s1[threadIdx.x+s]; s2[threadIdx.x] += s2[threadIdx.x+s]; }
        __syncthreads();
    }
    float mean = s1[0] / cols;
    float var  = s2[0] / cols - mean * mean;
    float rstd = rsqrtf(var + 1e-5f);
    float* orow = out + (size_t)blockIdx.x * cols;
    const float* rrow = res ? res + (size_t)blockIdx.x * cols : nullptr;
    for (int i = threadIdx.x; i < cols; i += 256) {
        float v = (row[i] - mean) * rstd;
        if (g)    v = v * g[i] + b[i];
        if (rrow) v += rrow[i];
        orow[i] = v;
    }
}

// ---------------- GEMM C = alpha * A[M,K] @ W[N,K]^T (+bias)(+addsrc)(+gelu)
// Tile 128x64, 256 threads, 8x4 per-thread accumulators, batched over
// gridDim.z with strides sA/sW/sC. M % 128 == 0, K % 16 == 0, any N.
__global__ void __launch_bounds__(256, 2)
gemm_nt(const float* __restrict__ A, int lda, size_t sA,
        const float* __restrict__ W, int ldw, size_t sW,
        const float* __restrict__ bias,
        const float* __restrict__ addsrc,
        float* __restrict__ C, int ldc, size_t sC,
        int N, int K, float alpha, int act)
{
    __shared__ float As[16][128];
    __shared__ float Ws[16][64];
    A += (size_t)blockIdx.z * sA;
    W += (size_t)blockIdx.z * sW;
    C += (size_t)blockIdx.z * sC;
    int bm = blockIdx.y * 128, bn = blockIdx.x * 64;
    int tx = threadIdx.x & 15;        // 0..15 -> 4 output cols each
    int ty = threadIdx.x >> 4;        // 0..15 -> 8 output rows each
    int tid = threadIdx.x;
    float acc[8][4] = {};
    for (int k0 = 0; k0 < K; k0 += 16) {
        #pragma unroll
        for (int i = 0; i < 8; i++) {           // 2048 A elems
            int e  = tid + i * 256;
            int mm = e >> 4, kk = e & 15;
            As[kk][mm] = A[(size_t)(bm + mm) * lda + k0 + kk];
        }
        #pragma unroll
        for (int i = 0; i < 4; i++) {           // 1024 W elems
            int e  = tid + i * 256;
            int mm = e >> 4, kk = e & 15;
            Ws[kk][mm] = (bn + mm < N) ? W[(size_t)(bn + mm) * ldw + k0 + kk] : 0.f;
        }
        __syncthreads();
        #pragma unroll
        for (int kk = 0; kk < 16; kk++) {
            float4 a0 = *reinterpret_cast<const float4*>(&As[kk][ty * 8]);
            float4 a1 = *reinterpret_cast<const float4*>(&As[kk][ty * 8 + 4]);
            float4 b4 = *reinterpret_cast<const float4*>(&Ws[kk][tx * 4]);
            float a[8] = {a0.x, a0.y, a0.z, a0.w, a1.x, a1.y, a1.z, a1.w};
            float b[4] = {b4.x, b4.y, b4.z, b4.w};
            #pragma unroll
            for (int i = 0; i < 8; i++)
                #pragma unroll
                for (int j = 0; j < 4; j++)
                    acc[i][j] += a[i] * b[j];
        }
        __syncthreads();
    }
    #pragma unroll
    for (int i = 0; i < 8; i++) {
        int r = bm + ty * 8 + i;
        #pragma unroll
        for (int j = 0; j < 4; j++) {
            int c = bn + tx * 4 + j;
            if (c < N) {
                float v = acc[i][j] * alpha;
                if (bias)   v += bias[c];
                if (act) {                       // tanh-approx GELU
                    float u = 0.7978845608028654f * (v + 0.044715f * v * v * v);
                    v = 0.5f * v * (1.f + tanhf(u));
                }
                if (addsrc) v += addsrc[(size_t)r * ldc + c];
                C[(size_t)r * ldc + c] = v;
            }
        }
    }
}

// ---------------- GEMM C = A[M,K] @ B[K,N] (B row-major), batched ----------
__global__ void __launch_bounds__(256, 2)
gemm_nn(const float* __restrict__ A, int lda, size_t sA,
        const float* __restrict__ B, int ldb, size_t sB,
        float* __restrict__ C, int ldc, size_t sC,
        int N, int K)
{
    __shared__ float As[16][128];
    __shared__ float Bs[16][64];
    A += (size_t)blockIdx.z * sA;
    B += (size_t)blockIdx.z * sB;
    C += (size_t)blockIdx.z * sC;
    int bm = blockIdx.y * 128, bn = blockIdx.x * 64;
    int tx = threadIdx.x & 15;
    int ty = threadIdx.x >> 4;
    int tid = threadIdx.x;
    float acc[8][4] = {};
    for (int k0 = 0; k0 < K; k0 += 16) {
        #pragma unroll
        for (int i = 0; i < 8; i++) {
            int e  = tid + i * 256;
            int mm = e >> 4, kk = e & 15;
            As[kk][mm] = A[(size_t)(bm + mm) * lda + k0 + kk];
        }
        #pragma unroll
        for (int i = 0; i < 4; i++) {           // 1024 B elems: 16 k x 64 n
            int e  = tid + i * 256;
            int kk = e >> 6, nn = e & 63;
            Bs[kk][nn] = (bn + nn < N) ? B[(size_t)(k0 + kk) * ldb + bn + nn] : 0.f;
        }
        __syncthreads();
        #pragma unroll
        for (int kk = 0; kk < 16; kk++) {
            float4 a0 = *reinterpret_cast<const float4*>(&As[kk][ty * 8]);
            float4 a1 = *reinterpret_cast<const float4*>(&As[kk][ty * 8 + 4]);
            float4 b4 = *reinterpret_cast<const float4*>(&Bs[kk][tx * 4]);
            float a[8] = {a0.x, a0.y, a0.z, a0.w, a1.x, a1.y, a1.z, a1.w};
            float b[4] = {b4.x, b4.y, b4.z, b4.w};
            #pragma unroll
            for (int i = 0; i < 8; i++)
                #pragma unroll
                for (int j = 0; j < 4; j++)
                    acc[i][j] += a[i] * b[j];
        }
        __syncthreads();
    }
    #pragma unroll
    for (int i = 0; i < 8; i++) {
        int r = bm + ty * 8 + i;
        #pragma unroll
        for (int j = 0; j < 4; j++) {
            int c = bn + tx * 4 + j;
            if (c < N) C[(size_t)r * ldc + c] = acc[i][j];
        }
    }
}

// ---------------- softmax over rows of length `cols` -----------------------
__global__ void softmax_rows(float* __restrict__ S, int cols)
{
    float* row = S + (size_t)blockIdx.x * cols;
    __shared__ float red[256];
    float mx = -1e30f;
    for (int i = threadIdx.x; i < cols; i += 256) mx = fmaxf(mx, row[i]);
    red[threadIdx.x] = mx; __syncthreads();
    for (int s = 128; s > 0; s >>= 1) {
        if (threadIdx.x < s) red[threadIdx.x] = fmaxf(red[threadIdx.x], red[threadIdx.x+s]);
        __syncthreads();
    }
    mx = red[0]; __syncthreads();
    float sum = 0.f;
    for (int i = threadIdx.x; i < cols; i += 256) {
        float e = __expf(row[i] - mx); row[i] = e; sum += e;
    }
    red[threadIdx.x] = sum; __syncthreads();
    for (int s = 128; s > 0; s >>= 1) {
        if (threadIdx.x < s) red[threadIdx.x] += red[threadIdx.x+s];
        __syncthreads();
    }
    float inv = 1.f / red[0];
    for (int i = threadIdx.x; i < cols; i += 256) row[i] *= inv;
}

// ---------------- depthwise causal conv (taps=4) ---------------------------
__global__ void conv_kernel(const float* __restrict__ w, const float* __restrict__ cb)
{
    int idx = blockIdx.x * blockDim.x + threadIdx.x;
    if (idx >= L * DI) return;
    int l = idx / DI, c = idx % DI;
    float s = cb[c];
    #pragma unroll
    for (int j = 0; j < 4; j++) {
        int t = l - 3 + j;
        if (t >= 0) s += w[c * 4 + j] * g_mx[(size_t)t * DI + c];
    }
    g_cv[idx] = s;
}

// ---------------- Bm / Cm: LN over 16-dim slices of xdbc -------------------
__global__ void bc16_kernel()
{
    int l = blockIdx.x * blockDim.x + threadIdx.x;
    if (l >= L) return;
    const float* r = g_xdbc + (size_t)l * 96;
    #pragma unroll
    for (int p = 0; p < 2; p++) {
        int off = 64 + p * 16;
        float s = 0.f, q = 0.f;
        #pragma unroll
        for (int i = 0; i < 16; i++) { float v = r[off + i]; s += v; q += v * v; }
        float mean = s * (1.f/16.f);
        float var  = q * (1.f/16.f) - mean * mean;
        float rstd = rsqrtf(var + 1e-5f);
        float* dst = (p == 0 ? g_Bm : g_Cm) + (size_t)l * 16;
        #pragma unroll
        for (int i = 0; i < 16; i++) dst[i] = (r[off + i] - mean) * rstd;
    }
}

// ---------------- scan prep: M = clip(exp(logA_min - logA), 1e-4, 1e4) -----
// (delta cancels out of the reference's M entirely; M is time-invariant)
__global__ void scan_prep(const float* __restrict__ A)
{
    __shared__ float sla[256];
    int t = threadIdx.x;
    int i = t >> 4, j = t & 15;
    float la = logf(fabsf(A[j * NST + i]) + 1e-8f);  // A_sub[i][j] = A[j][i]
    sla[t] = la;
    __syncthreads();
    for (int s = 128; s > 0; s >>= 1) {
        if (t < s) sla[t] = fminf(sla[t], sla[t+s]);
        __syncthreads();
    }
    float m = expf(sla[0] - la);
    g_M[i * NST + j] = fminf(fmaxf(m, 1e-4f), 1e4f);
}

// ---------------- sequential linear recurrence H_t = M H_{t-1} + B_t -------
__global__ void scan_kernel()
{
    int lane = threadIdx.x;
    float m[16];
    #pragma unroll
    for (int j = 0; j < 16; j++) m[j] = (lane < 16) ? g_M[lane * 16 + j] : 0.f;
    float h = (lane < 16) ? g_Bm[lane] : 0.f;
    if (lane < 16) g_Hall[lane] = h;
    for (int t = 1; t < L; t++) {
        float b = (lane < 16) ? g_Bm[(size_t)t * 16 + lane] : 0.f;
        float hn = b;
        #pragma unroll
        for (int j = 0; j < 16; j++) hn += m[j] * __shfl_sync(0xffffffffu, h, j);
        h = hn;
        if (lane < 16) g_Hall[(size_t)t * 16 + lane] = h;
    }
}

// ---------------- y = (H.C) * x + x*Dp, fused with the H.C dot -------------
__global__ void y_kernel(const float* __restrict__ Dp)
{
    int l = blockIdx.x;                 // one block per timestep
    __shared__ float hd;
    if (threadIdx.x == 0) {
        float s = 0.f;
        #pragma unroll
        for (int i = 0; i < 16; i++)
            s += g_Hall[(size_t)l * 16 + i] * g_Cm[(size_t)l * 16 + i];
        hd = s;
    }
    __syncthreads();
    float h = hd;
    for (int c = threadIdx.x; c < DI; c += blockDim.x) {
        float xv = g_mx[(size_t)l * DI + c];
        float yv = h * xv + xv * Dp[c];
        g_y[(size_t)l * DI + c] = fminf(fmaxf(yv, -1000.f), 1000.f);
    }
}

// ---------------------------------------------------------------------------
extern "C" void kernel_launch(void* const* d_in, const int* in_sizes, int n_in,
                              void* d_out, int out_size)
{
    const float* x     = (const float*)d_in[0];
    const float* Wq    = (const float*)d_in[1];
    const float* bq    = (const float*)d_in[2];
    const float* Wk    = (const float*)d_in[3];
    const float* bk    = (const float*)d_in[4];
    const float* Wv    = (const float*)d_in[5];
    const float* bv    = (const float*)d_in[6];
    const float* Wo    = (const float*)d_in[7];
    const float* bo    = (const float*)d_in[8];
    const float* fc1_w = (const float*)d_in[9];
    const float* fc1_b = (const float*)d_in[10];
    const float* fc2_w = (const float*)d_in[11];
    const float* fc2_b = (const float*)d_in[12];
    const float* in_w  = (const float*)d_in[13];
    const float* in_b  = (const float*)d_in[14];
    const float* cv_w  = (const float*)d_in[15];
    const float* cv_b  = (const float*)d_in[16];
    const float* xp_w  = (const float*)d_in[17];
    const float* xp_b  = (const float*)d_in[18];
    const float* A     = (const float*)d_in[19];
    const float* Dp    = (const float*)d_in[20];
    /* dt_p = d_in[21] — provably unused: delta cancels out of M */
    const float* out_w = (const float*)d_in[22];
    const float* out_b = (const float*)d_in[23];
    const float* g1    = (const float*)d_in[24];
    const float* be1   = (const float*)d_in[25];
    const float* g2    = (const float*)d_in[26];
    const float* be2   = (const float*)d_in[27];
    const float* g3    = (const float*)d_in[28];
    const float* be3   = (const float*)d_in[29];
    float* out = (float*)d_out;

    float *p_h, *p_q, *p_k, *p_v, *p_s, *p_ao, *p_x1, *p_mln, *p_mx, *p_cv,
          *p_xdbc, *p_y, *p_mo, *p_x2, *p_h3, *p_ff;
    cudaGetSymbolAddress((void**)&p_h,   g_h);
    cudaGetSymbolAddress((void**)&p_q,   g_q);
    cudaGetSymbolAddress((void**)&p_k,   g_k);
    cudaGetSymbolAddress((void**)&p_v,   g_v);
    cudaGetSymbolAddress((void**)&p_s,   g_s);
    cudaGetSymbolAddress((void**)&p_ao,  g_ao);
    cudaGetSymbolAddress((void**)&p_x1,  g_x1);
    cudaGetSymbolAddress((void**)&p_mln, g_mln);
    cudaGetSymbolAddress((void**)&p_mx,  g_mx);
    cudaGetSymbolAddress((void**)&p_cv,  g_cv);
    cudaGetSymbolAddress((void**)&p_xdbc,g_xdbc);
    cudaGetSymbolAddress((void**)&p_y,   g_y);
    cudaGetSymbolAddress((void**)&p_mo,  g_mo);
    cudaGetSymbolAddress((void**)&p_x2,  g_x2);
    cudaGetSymbolAddress((void**)&p_h3,  g_h3);
    cudaGetSymbolAddress((void**)&p_ff,  g_ff);

    auto grid = [](int M, int N, int Z) {
        return dim3((unsigned)((N + 63) / 64), (unsigned)(M / 128), (unsigned)Z);
    };

    // ===== attention =====
    ln_kernel<<<L, 256>>>(x, g1, be1, nullptr, p_h, DM);
    gemm_nt<<<grid(L, DM, 1), 256>>>(p_h, DM, 0, Wq, DM, 0, bq, nullptr, p_q, DM, 0, DM, DM, 1.f, 0);
    gemm_nt<<<grid(L, DM, 1), 256>>>(p_h, DM, 0, Wk, DM, 0, bk, nullptr, p_k, DM, 0, DM, DM, 1.f, 0);
    gemm_nt<<<grid(L, DM, 1), 256>>>(p_h, DM, 0, Wv, DM, 0, bv, nullptr, p_v, DM, 0, DM, DM, 1.f, 0);
    // scores: one batched launch over all 16 heads
    gemm_nt<<<grid(L, L, NH), 256>>>(p_q, DM, DK, p_k, DM, DK, nullptr, nullptr,
                                     p_s, L, (size_t)L * L, L, DK, 0.125f, 0);
    softmax_rows<<<NH * L, 256>>>(p_s, L);
    gemm_nn<<<grid(L, DK, NH), 256>>>(p_s, L, (size_t)L * L, p_v, DM, DK,
                                      p_ao, DM, DK, DK, L);
    gemm_nt<<<grid(L, DM, 1), 256>>>(p_ao, DM, 0, Wo, DM, 0, bo, x, p_x1, DM, 0, DM, DM, 1.f, 0);

    // ===== mamba =====
    ln_kernel<<<L, 256>>>(p_x1, g2, be2, nullptr, p_h, DM);
    ln_kernel<<<L, 256>>>(p_h, nullptr, nullptr, nullptr, p_mln, DM);
    gemm_nt<<<grid(L, DI, 1), 256>>>(p_mln, DM, 0, in_w, DM, 0, in_b, nullptr, p_mx, DI, 0, DI, DM, 1.f, 0);
    conv_kernel<<<(L * DI + 255) / 256, 256>>>(cv_w, cv_b);
    gemm_nt<<<grid(L, 96, 1), 256>>>(p_cv, DI, 0, xp_w, DI, 0, xp_b, nullptr, p_xdbc, 96, 0, 96, DI, 1.f, 0);
    ln_kernel<<<L, 256>>>(p_xdbc, nullptr, nullptr, nullptr, p_xdbc, 96);  // in-place OK
    bc16_kernel<<<(L + 255) / 256, 256>>>();
    scan_prep<<<1, 256>>>(A);
    scan_kernel<<<1, 32>>>();
    y_kernel<<<L, 256>>>(Dp);
    gemm_nt<<<grid(L, DM, 1), 256>>>(p_y, DI, 0, out_w, DI, 0, out_b, nullptr, p_mo, DM, 0, DM, DI, 1.f, 0);
    ln_kernel<<<L, 256>>>(p_mo, nullptr, nullptr, p_x1, p_x2, DM);  // x2 = x1 + LN(mo)

    // ===== FFN =====
    ln_kernel<<<L, 256>>>(p_x2, g3, be3, nullptr, p_h3, DM);
    gemm_nt<<<grid(L, DFF, 1), 256>>>(p_h3, DM, 0, fc1_w, DM, 0, fc1_b, nullptr, p_ff, DFF, 0, DFF, DM, 1.f, 1);
    gemm_nt<<<grid(L, DM, 1), 256>>>(p_ff, DFF, 0, fc2_w, DFF, 0, fc2_b, p_x2, out, DM, 0, DM, DFF, 1.f, 0);
}

// round 11
// speedup vs baseline: 2.2363x; 2.2363x over previous
#include <cuda_runtime.h>
#include <cuda_bf16.h>
#include <math.h>

#define L    2048
#define DM   1024
#define NH   16
#define DK   64
#define DFF  4096
#define DI   2048
#define NST  16

// ---------------- scratch (device globals; no allocation allowed) ----------
__device__ float g_h   [L*DM];
__device__ float g_q   [L*DM];
__device__ float g_k   [L*DM];
__device__ float g_v   [L*DM];
__device__ float g_s   [(size_t)NH*L*L];   // 256 MB attention scores
__device__ float g_ao  [L*DM];
__device__ float g_x1  [L*DM];
__device__ float g_mln [L*DM];
__device__ float g_mx  [L*DI];
__device__ float g_cv  [L*DI];
__device__ float g_xdbc[L*96];
__device__ float g_Bm  [L*NST];
__device__ float g_Cm  [L*NST];
__device__ float g_M   [NST*NST];
__device__ float g_Hall[L*NST];
__device__ float g_y   [L*DI];
__device__ float g_mo  [L*DM];
__device__ float g_x2  [L*DM];
__device__ float g_h3  [L*DM];
__device__ float g_ff  [(size_t)L*DFF];

// ---------------- helpers ---------------------------------------------------
__device__ __forceinline__ void bsplit(float x, __nv_bfloat16& h, __nv_bfloat16& l) {
    h = __float2bfloat16(x);
    l = __float2bfloat16(x - __bfloat162float(h));
}
__device__ __forceinline__ unsigned pack2(__nv_bfloat16 a, __nv_bfloat16 b) {
    __nv_bfloat162 p = __halves2bfloat162(a, b);   // .x = a (low half = even k)
    return *reinterpret_cast<unsigned*>(&p);
}

#define MMA_BF16(c, a, b)                                                      \
    asm volatile(                                                              \
        "mma.sync.aligned.m16n8k16.row.col.f32.bf16.bf16.f32 "                 \
        "{%0,%1,%2,%3}, {%4,%5,%6,%7}, {%8,%9}, {%0,%1,%2,%3};"                \
        : "+f"((c)[0]), "+f"((c)[1]), "+f"((c)[2]), "+f"((c)[3])               \
        : "r"((a)[0]), "r"((a)[1]), "r"((a)[2]), "r"((a)[3]),                  \
          "r"((b)[0]), "r"((b)[1]))

// ---------------- LayerNorm (optional affine, optional residual add) -------
__global__ void ln_kernel(const float* __restrict__ in,
                          const float* __restrict__ g,
                          const float* __restrict__ b,
                          const float* __restrict__ res,
                          float* __restrict__ out, int cols)
{
    __shared__ float s1[256], s2[256];
    const float* row = in + (size_t)blockIdx.x * cols;
    float sum = 0.f, sq = 0.f;
    for (int i = threadIdx.x; i < cols; i += 256) {
        float v = row[i]; sum += v; sq += v * v;
    }
    s1[threadIdx.x] = sum; s2[threadIdx.x] = sq;
    __syncthreads();
    for (int s = 128; s > 0; s >>= 1) {
        if (threadIdx.x < s) { s1[threadIdx.x] += s1[threadIdx.x+s]; s2[threadIdx.x] += s2[threadIdx.x+s]; }
        __syncthreads();
    }
    float mean = s1[0] / cols;
    float var  = s2[0] / cols - mean * mean;
    float rstd = rsqrtf(var + 1e-5f);
    float* orow = out + (size_t)blockIdx.x * cols;
    const float* rrow = res ? res + (size_t)blockIdx.x * cols : nullptr;
    for (int i = threadIdx.x; i < cols; i += 256) {
        float v = (row[i] - mean) * rstd;
        if (g)    v = v * g[i] + b[i];
        if (rrow) v += rrow[i];
        orow[i] = v;
    }
}

// ---------------- compensated-bf16 tensor-core GEMM -------------------------
// BT=true : C = alpha * A[M,K] @ B[N,K]^T  (B row-major, "nt")
// BT=false: C = alpha * A[M,K] @ B[K,N]    (B row-major, "nn"; needs N%4==0)
// Each operand split x = hi + lo (bf16 each); C = Ah*Bh + Ah*Bl + Al*Bh in
// fp32 accumulators (per-element rep error ~2^-18; lo*lo term neglected).
// Tile 128x128x32, 256 threads = 8 warps of 64x32, m16n8k16 bf16 mma.
// Batched over blockIdx.z with strides sA/sB/sC. M%128==0, K%32==0.
// smem rows have stride 20 words: fragment loads are bank-conflict-free
// (20*r mod 32 spans {0,20,8,28,16,4,24,12} over 8 rows, x4 tg offsets).
template<bool BT>
__global__ void __launch_bounds__(256, 2)
gemm_tc(const float* __restrict__ A, int lda, size_t sA,
        const float* __restrict__ B, int ldb, size_t sB,
        const float* __restrict__ bias,
        const float* __restrict__ addsrc,
        float* __restrict__ C, int ldc, size_t sC,
        int N, int K, float alpha, int act)
{
    __shared__ unsigned Ah[128 * 20], Al[128 * 20];   // [m][kpair], 16 pairs + 4 pad
    __shared__ unsigned Bh[128 * 20], Bl[128 * 20];   // [n][kpair] (both layouts n-major)
    A += (size_t)blockIdx.z * sA;
    B += (size_t)blockIdx.z * sB;
    C += (size_t)blockIdx.z * sC;
    const int bm = blockIdx.y * 128, bn = blockIdx.x * 128;
    const int tid = threadIdx.x, lane = tid & 31, wid = tid >> 5;
    const int wm = (wid >> 2) * 64;        // warp row offset {0,64}
    const int wn = (wid & 3) * 32;         // warp col offset {0,32,64,96}
    const int g  = lane >> 2, tg = lane & 3;

    float acc[4][4][4] = {};

    for (int k0 = 0; k0 < K; k0 += 32) {
        // ---- fill A: 128 rows x 32 k; float4 load, split, pack bf16x2 ----
        #pragma unroll
        for (int i = 0; i < 4; i++) {
            int f = tid + i * 256;
            int m = f >> 3, kq = (f & 7) * 4;
            float4 v = *reinterpret_cast<const float4*>(&A[(size_t)(bm + m) * lda + k0 + kq]);
            __nv_bfloat16 h0,l0,h1,l1,h2,l2,h3,l3;
            bsplit(v.x,h0,l0); bsplit(v.y,h1,l1); bsplit(v.z,h2,l2); bsplit(v.w,h3,l3);
            int base = m * 20 + (kq >> 1);
            Ah[base] = pack2(h0,h1); Ah[base+1] = pack2(h2,h3);
            Al[base] = pack2(l0,l1); Al[base+1] = pack2(l2,l3);
        }
        // ---- fill B ----
        if (BT) {
            #pragma unroll
            for (int i = 0; i < 4; i++) {
                int f = tid + i * 256;
                int n = f >> 3, kq = (f & 7) * 4;
                float4 v = make_float4(0.f, 0.f, 0.f, 0.f);
                if (bn + n < N)
                    v = *reinterpret_cast<const float4*>(&B[(size_t)(bn + n) * ldb + k0 + kq]);
                __nv_bfloat16 h0,l0,h1,l1,h2,l2,h3,l3;
                bsplit(v.x,h0,l0); bsplit(v.y,h1,l1); bsplit(v.z,h2,l2); bsplit(v.w,h3,l3);
                int base = n * 20 + (kq >> 1);
                Bh[base] = pack2(h0,h1); Bh[base+1] = pack2(h2,h3);
                Bl[base] = pack2(l0,l1); Bl[base+1] = pack2(l2,l3);
            }
        } else {
            // transpose fill: each thread takes one n and 4 consecutive k,
            // so the packed (k even, k odd) words are thread-private.
            #pragma unroll
            for (int i = 0; i < 4; i++) {
                int f = tid + i * 256;             // 1024 slots = 128 n x 8 kquads
                int n = f & 127, kk = (f >> 7) * 4;
                float v0 = 0.f, v1 = 0.f, v2 = 0.f, v3 = 0.f;
                if (bn + n < N) {                  // N%4 not needed here; scalar loads
                    const float* bp = &B[(size_t)(k0 + kk) * ldb + bn + n];
                    v0 = bp[0]; v1 = bp[(size_t)ldb]; v2 = bp[(size_t)2 * ldb]; v3 = bp[(size_t)3 * ldb];
                }
                __nv_bfloat16 h0,l0,h1,l1,h2,l2,h3,l3;
                bsplit(v0,h0,l0); bsplit(v1,h1,l1); bsplit(v2,h2,l2); bsplit(v3,h3,l3);
                int base = n * 20 + (kk >> 1);
                Bh[base] = pack2(h0,h1); Bh[base+1] = pack2(h2,h3);
                Bl[base] = pack2(l0,l1); Bl[base+1] = pack2(l2,l3);
            }
        }
        __syncthreads();
        #pragma unroll
        for (int s = 0; s < 2; s++) {              // two k16 steps per 32-k chunk
            const int p = s * 8;                    // base k-pair of this step
            unsigned ah[4][4], al[4][4], bh[4][2], bl[4][2];
            #pragma unroll
            for (int mt = 0; mt < 4; mt++) {
                int r = wm + mt * 16 + g;
                ah[mt][0] = Ah[r * 20 + p + tg];
                ah[mt][1] = Ah[(r + 8) * 20 + p + tg];
                ah[mt][2] = Ah[r * 20 + p + tg + 4];
                ah[mt][3] = Ah[(r + 8) * 20 + p + tg + 4];
                al[mt][0] = Al[r * 20 + p + tg];
                al[mt][1] = Al[(r + 8) * 20 + p + tg];
                al[mt][2] = Al[r * 20 + p + tg + 4];
                al[mt][3] = Al[(r + 8) * 20 + p + tg + 4];
            }
            #pragma unroll
            for (int nt = 0; nt < 4; nt++) {
                int n = wn + nt * 8 + g;
                bh[nt][0] = Bh[n * 20 + p + tg];
                bh[nt][1] = Bh[n * 20 + p + tg + 4];
                bl[nt][0] = Bl[n * 20 + p + tg];
                bl[nt][1] = Bl[n * 20 + p + tg + 4];
            }
            #pragma unroll
            for (int mt = 0; mt < 4; mt++)
                #pragma unroll
                for (int nt = 0; nt < 4; nt++) {
                    float* c = acc[mt][nt];
                    MMA_BF16(c, ah[mt], bh[nt]);
                    MMA_BF16(c, ah[mt], bl[nt]);
                    MMA_BF16(c, al[mt], bh[nt]);
                }
        }
        __syncthreads();
    }
    // ---- epilogue ----
    #pragma unroll
    for (int mt = 0; mt < 4; mt++) {
        #pragma unroll
        for (int nt = 0; nt < 4; nt++) {
            int r0 = bm + wm + mt * 16 + g;
            int cb = bn + wn + nt * 8 + tg * 2;
            float* c = acc[mt][nt];
            #pragma unroll
            for (int h = 0; h < 4; h++) {
                int r  = r0 + (h >> 1) * 8;
                int cc = cb + (h & 1);
                if (cc < N) {
                    float v = c[h] * alpha;
                    if (bias) v += bias[cc];
                    if (act) {                       // tanh-approx GELU
                        float u = 0.7978845608028654f * (v + 0.044715f * v * v * v);
                        v = 0.5f * v * (1.f + tanhf(u));
                    }
                    if (addsrc) v += addsrc[(size_t)r * ldc + cc];
                    C[(size_t)r * ldc + cc] = v;
                }
            }
        }
    }
}

// ---------------- softmax over rows of 2048, register-cached ---------------
__global__ void softmax_rows(float* __restrict__ S)
{
    float* row = S + (size_t)blockIdx.x * L;
    __shared__ float red[256];
    float v[8];
    float mx = -1e30f;
    #pragma unroll
    for (int i = 0; i < 8; i++) {
        v[i] = row[threadIdx.x + i * 256];
        mx = fmaxf(mx, v[i]);
    }
    red[threadIdx.x] = mx; __syncthreads();
    for (int s = 128; s > 0; s >>= 1) {
        if (threadIdx.x < s) red[threadIdx.x] = fmaxf(red[threadIdx.x], red[threadIdx.x+s]);
        __syncthreads();
    }
    mx = red[0]; __syncthreads();
    float sum = 0.f;
    #pragma unroll
    for (int i = 0; i < 8; i++) {
        v[i] = __expf(v[i] - mx);
        sum += v[i];
    }
    red[threadIdx.x] = sum; __syncthreads();
    for (int s = 128; s > 0; s >>= 1) {
        if (threadIdx.x < s) red[threadIdx.x] += red[threadIdx.x+s];
        __syncthreads();
    }
    float inv = 1.f / red[0];
    #pragma unroll
    for (int i = 0; i < 8; i++)
        row[threadIdx.x + i * 256] = v[i] * inv;
}

// ---------------- depthwise causal conv (taps=4) ---------------------------
__global__ void conv_kernel(const float* __restrict__ w, const float* __restrict__ cb)
{
    int idx = blockIdx.x * blockDim.x + threadIdx.x;
    if (idx >= L * DI) return;
    int l = idx / DI, c = idx % DI;
    float s = cb[c];
    #pragma unroll
    for (int j = 0; j < 4; j++) {
        int t = l - 3 + j;
        if (t >= 0) s += w[c * 4 + j] * g_mx[(size_t)t * DI + c];
    }
    g_cv[idx] = s;
}

// ---------------- Bm / Cm: LN over 16-dim slices of xdbc -------------------
__global__ void bc16_kernel()
{
    int l = blockIdx.x * blockDim.x + threadIdx.x;
    if (l >= L) return;
    const float* r = g_xdbc + (size_t)l * 96;
    #pragma unroll
    for (int p = 0; p < 2; p++) {
        int off = 64 + p * 16;
        float s = 0.f, q = 0.f;
        #pragma unroll
        for (int i = 0; i < 16; i++) { float v = r[off + i]; s += v; q += v * v; }
        float mean = s * (1.f/16.f);
        float var  = q * (1.f/16.f) - mean * mean;
        float rstd = rsqrtf(var + 1e-5f);
        float* dst = (p == 0 ? g_Bm : g_Cm) + (size_t)l * 16;
        #pragma unroll
        for (int i = 0; i < 16; i++) dst[i] = (r[off + i] - mean) * rstd;
    }
}

// ---------------- scan prep: M = clip(exp(logA_min - logA), 1e-4, 1e4) -----
// (delta cancels out of the reference's M entirely; M is time-invariant)
__global__ void scan_prep(const float* __restrict__ A)
{
    __shared__ float sla[256];
    int t = threadIdx.x;
    int i = t >> 4, j = t & 15;
    float la = logf(fabsf(A[j * NST + i]) + 1e-8f);  // A_sub[i][j] = A[j][i]
    sla[t] = la;
    __syncthreads();
    for (int s = 128; s > 0; s >>= 1) {
        if (t < s) sla[t] = fminf(sla[t], sla[t+s]);
        __syncthreads();
    }
    float m = expf(sla[0] - la);
    g_M[i * NST + j] = fminf(fmaxf(m, 1e-4f), 1e4f);
}

// ---------------- sequential linear recurrence H_t = M H_{t-1} + B_t -------
__global__ void scan_kernel()
{
    int lane = threadIdx.x;
    float m[16];
    #pragma unroll
    for (int j = 0; j < 16; j++) m[j] = (lane < 16) ? g_M[lane * 16 + j] : 0.f;
    float h = (lane < 16) ? g_Bm[lane] : 0.f;
    if (lane < 16) g_Hall[lane] = h;
    for (int t = 1; t < L; t++) {
        float b = (lane < 16) ? g_Bm[(size_t)t * 16 + lane] : 0.f;
        float hn = b;
        #pragma unroll
        for (int j = 0; j < 16; j++) hn += m[j] * __shfl_sync(0xffffffffu, h, j);
        h = hn;
        if (lane < 16) g_Hall[(size_t)t * 16 + lane] = h;
    }
}

// ---------------- y = (H.C) * x + x*Dp, fused with the H.C dot -------------
__global__ void y_kernel(const float* __restrict__ Dp)
{
    int l = blockIdx.x;                 // one block per timestep
    __shared__ float hd;
    if (threadIdx.x == 0) {
        float s = 0.f;
        #pragma unroll
        for (int i = 0; i < 16; i++)
            s += g_Hall[(size_t)l * 16 + i] * g_Cm[(size_t)l * 16 + i];
        hd = s;
    }
    __syncthreads();
    float h = hd;
    for (int c = threadIdx.x; c < DI; c += blockDim.x) {
        float xv = g_mx[(size_t)l * DI + c];
        float yv = h * xv + xv * Dp[c];
        g_y[(size_t)l * DI + c] = fminf(fmaxf(yv, -1000.f), 1000.f);
    }
}

// ---------------------------------------------------------------------------
extern "C" void kernel_launch(void* const* d_in, const int* in_sizes, int n_in,
                              void* d_out, int out_size)
{
    const float* x     = (const float*)d_in[0];
    const float* Wq    = (const float*)d_in[1];
    const float* bq    = (const float*)d_in[2];
    const float* Wk    = (const float*)d_in[3];
    const float* bk    = (const float*)d_in[4];
    const float* Wv    = (const float*)d_in[5];
    const float* bv    = (const float*)d_in[6];
    const float* Wo    = (const float*)d_in[7];
    const float* bo    = (const float*)d_in[8];
    const float* fc1_w = (const float*)d_in[9];
    const float* fc1_b = (const float*)d_in[10];
    const float* fc2_w = (const float*)d_in[11];
    const float* fc2_b = (const float*)d_in[12];
    const float* in_w  = (const float*)d_in[13];
    const float* in_b  = (const float*)d_in[14];
    const float* cv_w  = (const float*)d_in[15];
    const float* cv_b  = (const float*)d_in[16];
    const float* xp_w  = (const float*)d_in[17];
    const float* xp_b  = (const float*)d_in[18];
    const float* A     = (const float*)d_in[19];
    const float* Dp    = (const float*)d_in[20];
    /* dt_p = d_in[21] — provably unused: delta cancels out of M */
    const float* out_w = (const float*)d_in[22];
    const float* out_b = (const float*)d_in[23];
    const float* g1    = (const float*)d_in[24];
    const float* be1   = (const float*)d_in[25];
    const float* g2    = (const float*)d_in[26];
    const float* be2   = (const float*)d_in[27];
    const float* g3    = (const float*)d_in[28];
    const float* be3   = (const float*)d_in[29];
    float* out = (float*)d_out;

    float *p_h, *p_q, *p_k, *p_v, *p_s, *p_ao, *p_x1, *p_mln, *p_mx, *p_cv,
          *p_xdbc, *p_y, *p_mo, *p_x2, *p_h3, *p_ff;
    cudaGetSymbolAddress((void**)&p_h,   g_h);
    cudaGetSymbolAddress((void**)&p_q,   g_q);
    cudaGetSymbolAddress((void**)&p_k,   g_k);
    cudaGetSymbolAddress((void**)&p_v,   g_v);
    cudaGetSymbolAddress((void**)&p_s,   g_s);
    cudaGetSymbolAddress((void**)&p_ao,  g_ao);
    cudaGetSymbolAddress((void**)&p_x1,  g_x1);
    cudaGetSymbolAddress((void**)&p_mln, g_mln);
    cudaGetSymbolAddress((void**)&p_mx,  g_mx);
    cudaGetSymbolAddress((void**)&p_cv,  g_cv);
    cudaGetSymbolAddress((void**)&p_xdbc,g_xdbc);
    cudaGetSymbolAddress((void**)&p_y,   g_y);
    cudaGetSymbolAddress((void**)&p_mo,  g_mo);
    cudaGetSymbolAddress((void**)&p_x2,  g_x2);
    cudaGetSymbolAddress((void**)&p_h3,  g_h3);
    cudaGetSymbolAddress((void**)&p_ff,  g_ff);

    auto grid = [](int M, int N, int Z) {
        return dim3((unsigned)((N + 127) / 128), (unsigned)(M / 128), (unsigned)Z);
    };

    // ===== attention =====
    ln_kernel<<<L, 256>>>(x, g1, be1, nullptr, p_h, DM);
    gemm_tc<true><<<grid(L, DM, 1), 256>>>(p_h, DM, 0, Wq, DM, 0, bq, nullptr, p_q, DM, 0, DM, DM, 1.f, 0);
    gemm_tc<true><<<grid(L, DM, 1), 256>>>(p_h, DM, 0, Wk, DM, 0, bk, nullptr, p_k, DM, 0, DM, DM, 1.f, 0);
    gemm_tc<true><<<grid(L, DM, 1), 256>>>(p_h, DM, 0, Wv, DM, 0, bv, nullptr, p_v, DM, 0, DM, DM, 1.f, 0);
    // scores: one batched launch over all 16 heads
    gemm_tc<true><<<grid(L, L, NH), 256>>>(p_q, DM, DK, p_k, DM, DK, nullptr, nullptr,
                                           p_s, L, (size_t)L * L, L, DK, 0.125f, 0);
    softmax_rows<<<NH * L, 256>>>(p_s);
    // P @ V, batched over heads
    gemm_tc<false><<<grid(L, DK, NH), 256>>>(p_s, L, (size_t)L * L, p_v, DM, DK, nullptr, nullptr,
                                             p_ao, DM, DK, DK, L, 1.f, 0);
    gemm_tc<true><<<grid(L, DM, 1), 256>>>(p_ao, DM, 0, Wo, DM, 0, bo, x, p_x1, DM, 0, DM, DM, 1.f, 0);

    // ===== mamba =====
    ln_kernel<<<L, 256>>>(p_x1, g2, be2, nullptr, p_h, DM);
    ln_kernel<<<L, 256>>>(p_h, nullptr, nullptr, nullptr, p_mln, DM);
    gemm_tc<true><<<grid(L, DI, 1), 256>>>(p_mln, DM, 0, in_w, DM, 0, in_b, nullptr, p_mx, DI, 0, DI, DM, 1.f, 0);
    conv_kernel<<<(L * DI + 255) / 256, 256>>>(cv_w, cv_b);
    gemm_tc<true><<<grid(L, 96, 1), 256>>>(p_cv, DI, 0, xp_w, DI, 0, xp_b, nullptr, p_xdbc, 96, 0, 96, DI, 1.f, 0);
    ln_kernel<<<L, 256>>>(p_xdbc, nullptr, nullptr, nullptr, p_xdbc, 96);  // in-place OK
    bc16_kernel<<<(L + 255) / 256, 256>>>();
    scan_prep<<<1, 256>>>(A);
    scan_kernel<<<1, 32>>>();
    y_kernel<<<L, 256>>>(Dp);
    gemm_tc<true><<<grid(L, DM, 1), 256>>>(p_y, DI, 0, out_w, DI, 0, out_b, nullptr, p_mo, DM, 0, DM, DI, 1.f, 0);
    ln_kernel<<<L, 256>>>(p_mo, nullptr, nullptr, p_x1, p_x2, DM);  // x2 = x1 + LN(mo)

    // ===== FFN =====
    ln_kernel<<<L, 256>>>(p_x2, g3, be3, nullptr, p_h3, DM);
    gemm_tc<true><<<grid(L, DFF, 1), 256>>>(p_h3, DM, 0, fc1_w, DM, 0, fc1_b, nullptr, p_ff, DFF, 0, DFF, DM, 1.f, 1);
    gemm_tc<true><<<grid(L, DM, 1), 256>>>(p_ff, DFF, 0, fc2_w, DFF, 0, fc2_b, p_x2, out, DM, 0, DM, DFF, 1.f, 0);
}